// round 1
// baseline (speedup 1.0000x reference)
#include <cuda_runtime.h>

// GlitchSampler: masked scatter of random glitch windows into X, plus y labels.
//
// Shapes (from reference):
//   X        [B=512, C=2, K=4096] f32
//   y        [B=512]              f32
//   glitch_h [NG=2048, T=16384]   f32
//   glitch_l [NG=2048, T=16384]   f32
//   masks    [C=2, B=512]         (bool in jax; assumed int32 on the wire)
//   idx      [C=2, B=512]         int32
//   starts   [C=2, B=512]         int32
// Output: concat(Xo.flatten(), yo.flatten()) -> 512*2*4096 + 512 f32.

#define Bn 512
#define Cn 2
#define Kn 4096
#define Tn 16384
#define MIN_START 3584

__global__ void glitch_sampler_kernel(const float* __restrict__ X,
                                      const float* __restrict__ y,
                                      const float* __restrict__ gh,
                                      const float* __restrict__ gl,
                                      const int*   __restrict__ masks,
                                      const int*   __restrict__ idx,
                                      const int*   __restrict__ starts,
                                      float* __restrict__ out)
{
    const int row = blockIdx.x;                 // 0 .. B*C-1, then one tail block for y
    if (row < Bn * Cn) {
        const int b = row / Cn;
        const int c = row % Cn;
        const int cb = c * Bn + b;
        const bool m = masks[cb] != 0;
        float* __restrict__ dst = out + (long)row * Kn;

        if (!m) {
            // plain X copy, fully aligned float4 both sides
            const float4* __restrict__ src4 = (const float4*)(X + (long)row * Kn);
            float4* __restrict__ dst4 = (float4*)dst;
            #pragma unroll 4
            for (int k = threadIdx.x; k < Kn / 4; k += blockDim.x)
                dst4[k] = src4[k];
        } else {
            // gather 4096-float window from glitch row; source is float-aligned only
            const float* __restrict__ g = (c == 0) ? gh : gl;
            const long gbase = (long)idx[cb] * Tn + (starts[cb] + MIN_START);
            const float* __restrict__ src = g + gbase;
            float4* __restrict__ dst4 = (float4*)dst;
            #pragma unroll 2
            for (int k4 = threadIdx.x; k4 < Kn / 4; k4 += blockDim.x) {
                const int k = k4 * 4;
                float4 v;
                v.x = __ldg(src + k + 0);
                v.y = __ldg(src + k + 1);
                v.z = __ldg(src + k + 2);
                v.w = __ldg(src + k + 3);
                dst4[k4] = v;
            }
        }
    } else {
        // tail block: y output
        for (int b = threadIdx.x; b < Bn; b += blockDim.x) {
            float v = y[b];
            if (masks[0 * Bn + b] != 0) v -= 2.0f;
            if (masks[1 * Bn + b] != 0) v -= 4.0f;
            out[(long)Bn * Cn * Kn + b] = v;
        }
    }
}

extern "C" void kernel_launch(void* const* d_in, const int* in_sizes, int n_in,
                              void* d_out, int out_size)
{
    const float* X      = (const float*)d_in[0];
    const float* y      = (const float*)d_in[1];
    const float* gh     = (const float*)d_in[2];
    const float* gl     = (const float*)d_in[3];
    const int*   masks  = (const int*)  d_in[4];
    const int*   idx    = (const int*)  d_in[5];
    const int*   starts = (const int*)  d_in[6];
    float* out = (float*)d_out;

    const int nblocks = Bn * Cn + 1;   // 1024 row blocks + 1 y block
    glitch_sampler_kernel<<<nblocks, 256>>>(X, y, gh, gl, masks, idx, starts, out);
}

// round 2
// speedup vs baseline: 1.0218x; 1.0218x over previous
#include <cuda_runtime.h>

// GlitchSampler: masked scatter of random glitch windows into X, plus y labels.
// Latency-bound data movement -> maximize per-thread MLP: batch ALL loads
// before ANY store, fully unrolled, no loop.
//
// Shapes:
//   X        [B=512, C=2, K=4096] f32
//   y        [B=512]              f32
//   glitch_h [NG=2048, T=16384]   f32
//   glitch_l [NG=2048, T=16384]   f32
//   masks/idx/starts [C=2, B=512] int32
// Output: concat(Xo.flatten(), yo.flatten()) = 512*2*4096 + 512 f32.

#define Bn 512
#define Cn 2
#define Kn 4096
#define Tn 16384
#define MIN_START 3584

__global__ void __launch_bounds__(256)
glitch_sampler_kernel(const float* __restrict__ X,
                      const float* __restrict__ y,
                      const float* __restrict__ gh,
                      const float* __restrict__ gl,
                      const int*   __restrict__ masks,
                      const int*   __restrict__ idx,
                      const int*   __restrict__ starts,
                      float* __restrict__ out)
{
    const int row = blockIdx.x;                  // 0..1023 rows, block 1024 = y tail
    if (row < Bn * Cn) {
        const int b  = row >> 1;                 // X layout [B, C, K] -> row = b*2 + c
        const int c  = row & 1;
        const int cb = c * Bn + b;               // masks/idx/starts are [C, B]
        const bool m = masks[cb] != 0;

        const int tid = threadIdx.x;             // 256 threads, 4 float4 each
        float4* __restrict__ dst4 = (float4*)out + (long)row * (Kn / 4) + tid;

        float4 v0, v1, v2, v3;

        if (!m) {
            // aligned streaming copy of the X row
            const float4* __restrict__ s4 =
                (const float4*)X + (long)row * (Kn / 4) + tid;
            v0 = __ldcs(s4 +   0);
            v1 = __ldcs(s4 + 256);
            v2 = __ldcs(s4 + 512);
            v3 = __ldcs(s4 + 768);
        } else {
            // gather 4096-float window from a random glitch row.
            // Source is only float-aligned -> 16 independent scalar loads,
            // all issued before the stores (MLP = 16 per thread).
            const float* __restrict__ g = (c == 0) ? gh : gl;
            const float* __restrict__ src =
                g + (long)idx[cb] * Tn + (starts[cb] + MIN_START) + tid * 4;

            float f[16];
            #pragma unroll
            for (int i = 0; i < 4; ++i) {
                #pragma unroll
                for (int j = 0; j < 4; ++j)
                    f[i * 4 + j] = __ldcs(src + i * 1024 + j);
            }
            v0 = make_float4(f[0],  f[1],  f[2],  f[3]);
            v1 = make_float4(f[4],  f[5],  f[6],  f[7]);
            v2 = make_float4(f[8],  f[9],  f[10], f[11]);
            v3 = make_float4(f[12], f[13], f[14], f[15]);
        }

        dst4[  0] = v0;
        dst4[256] = v1;
        dst4[512] = v2;
        dst4[768] = v3;
    } else {
        // tail block: y output
        for (int b = threadIdx.x; b < Bn; b += blockDim.x) {
            float v = y[b];
            if (masks[0 * Bn + b] != 0) v -= 2.0f;
            if (masks[1 * Bn + b] != 0) v -= 4.0f;
            out[(long)Bn * Cn * Kn + b] = v;
        }
    }
}

extern "C" void kernel_launch(void* const* d_in, const int* in_sizes, int n_in,
                              void* d_out, int out_size)
{
    const float* X      = (const float*)d_in[0];
    const float* y      = (const float*)d_in[1];
    const float* gh     = (const float*)d_in[2];
    const float* gl     = (const float*)d_in[3];
    const int*   masks  = (const int*)  d_in[4];
    const int*   idx    = (const int*)  d_in[5];
    const int*   starts = (const int*)  d_in[6];
    float* out = (float*)d_out;

    glitch_sampler_kernel<<<Bn * Cn + 1, 256>>>(X, y, gh, gl, masks, idx, starts, out);
}